// round 1
// baseline (speedup 1.0000x reference)
#include <cuda_runtime.h>
#include <math.h>

#define BSZ 32
#define NXS 16384
#define IN_DIM 3
#define DIMC 64
#define NJ 16
#define MODE 128
#define RANKR 4
#define FCD 128
#define N_LAYERS 3

#define XH_SPLITS 16
#define Y_SPLITS 8

// ---------------- scratch (device globals; no allocations) ----------------
__device__ float g_h [BSZ*DIMC*NXS];                 // 128 MB
__device__ float g_h2[BSZ*DIMC*NXS];                 // 128 MB
__device__ float g_basesT[MODE*NXS];                 // 8 MB
__device__ float g_HT[NJ*MODE*MODE];                 // H^T: [j][l][k]
__device__ float g_xh [BSZ*DIMC*MODE];               // (b,c,k)
__device__ float g_xhp[XH_SPLITS*BSZ*DIMC*MODE];     // split partials
__device__ float g_xh1[BSZ*DIMC*NJ*MODE];            // (b, i*16+j, k)
__device__ float g_WrT[NJ*DIMC*DIMC];                // (p=i*16+j, o)
__device__ float g_y  [BSZ*DIMC*MODE];
__device__ float g_yp [Y_SPLITS*BSZ*DIMC*MODE];

__device__ __forceinline__ float gelu_f(float v){
    return 0.5f * v * (1.0f + erff(v * 0.70710678118654752440f));
}

// ---------------- bases transpose: basesT[k][x] = bases[x][k] -------------
__global__ void k_transpose(const float* __restrict__ bases){
    __shared__ float t[32][33];
    int x0 = blockIdx.x * 32, k0 = blockIdx.y * 32;
    for (int i = threadIdx.y; i < 32; i += 8)
        t[i][threadIdx.x] = bases[(size_t)(x0 + i) * MODE + k0 + threadIdx.x];
    __syncthreads();
    for (int i = threadIdx.y; i < 32; i += 8)
        g_basesT[(size_t)(k0 + i) * NXS + x0 + threadIdx.x] = t[threadIdx.x][i];
}

// ---------------- H^T build: HT[j][l][k] = H[j][k][l] ----------------------
__global__ void k_buildHT(const float* __restrict__ Do, const float* __restrict__ Di,
                          const float* __restrict__ pr, const float* __restrict__ A,
                          const float* __restrict__ Bm){
    int j = blockIdx.x, l = blockIdx.y, k = threadIdx.x;
    float s = Do[j*MODE + k] * Di[j*MODE + l] * pr[k*MODE + l];
    #pragma unroll
    for (int r = 0; r < RANKR; r++)
        s += A[(j*RANKR + r)*MODE + k] * Bm[(j*RANKR + r)*MODE + l];
    g_HT[((size_t)j*MODE + l)*MODE + k] = s;
}

// ---------------- fc0: h[b,c,x] = x[b,x,:] @ W0[:,c] + b0[c] ---------------
__global__ void k_fc0(const float* __restrict__ x, const float* __restrict__ W0,
                      const float* __restrict__ b0){
    int idx = blockIdx.x * 256 + threadIdx.x;           // < 32*64*16384
    int xp = idx & (NXS-1);
    int c  = (idx >> 14) & (DIMC-1);
    int b  = idx >> 20;
    const float* xr = &x[((size_t)b*NXS + xp)*IN_DIM];
    float s = b0[c] + xr[0]*W0[0*DIMC+c] + xr[1]*W0[1*DIMC+c] + xr[2]*W0[2*DIMC+c];
    g_h[idx] = s;
}

// ---- microkernel body shared by several GEMMs: 64x128 tile, 256 thr ------
#define MICRO_FMA(As,Bs,kk,acc,rg,cg)                                  \
    {                                                                   \
        float a_[8];                                                    \
        _Pragma("unroll")                                               \
        for (int i_ = 0; i_ < 8; i_++) a_[i_] = As[kk][rg*8 + i_];      \
        float4 bv_ = *(const float4*)&Bs[kk][cg*4];                     \
        _Pragma("unroll")                                               \
        for (int i_ = 0; i_ < 8; i_++){                                 \
            acc[i_][0] += a_[i_]*bv_.x; acc[i_][1] += a_[i_]*bv_.y;     \
            acc[i_][2] += a_[i_]*bv_.z; acc[i_][3] += a_[i_]*bv_.w;     \
        }                                                               \
    }

// ---------------- xh split-K GEMM: xh[b,c,k] = sum_x h[b,c,x] wbases[x,k] --
__global__ void __launch_bounds__(256) k_xh_part(const float* __restrict__ hin,
                                                 const float* __restrict__ wbases){
    int m0 = blockIdx.x * 64;                 // row tile (b*64)
    int split = blockIdx.y;                   // 0..15
    int k0 = split * (NXS / XH_SPLITS);       // 1024-chunk
    __shared__ float As[16][65];
    __shared__ float Bs[16][128];
    int tid = threadIdx.x, rg = tid >> 5, cg = tid & 31;
    float acc[8][4] = {};
    for (int kt = 0; kt < (NXS/XH_SPLITS)/16; kt++){
        int c = tid >> 2, kk4 = (tid & 3) * 4;
        float4 av = *(const float4*)&hin[(size_t)(m0 + c)*NXS + k0 + kt*16 + kk4];
        int kkB = tid >> 4, n8 = (tid & 15) * 8;
        const float* bsrc = &wbases[(size_t)(k0 + kt*16 + kkB)*MODE + n8];
        float4 bv0 = *(const float4*)bsrc, bv1 = *(const float4*)(bsrc + 4);
        __syncthreads();
        As[kk4+0][c]=av.x; As[kk4+1][c]=av.y; As[kk4+2][c]=av.z; As[kk4+3][c]=av.w;
        *(float4*)&Bs[kkB][n8] = bv0; *(float4*)&Bs[kkB][n8+4] = bv1;
        __syncthreads();
        #pragma unroll
        for (int kk = 0; kk < 16; kk++) MICRO_FMA(As,Bs,kk,acc,rg,cg)
    }
    #pragma unroll
    for (int i = 0; i < 8; i++){
        float4 v = make_float4(acc[i][0],acc[i][1],acc[i][2],acc[i][3]);
        *(float4*)&g_xhp[(size_t)split*(BSZ*DIMC*MODE) + (size_t)(m0 + rg*8 + i)*MODE + cg*4] = v;
    }
}

__global__ void k_reduce_xh(){
    int i = blockIdx.x * 256 + threadIdx.x;   // < 262144
    float s = 0.f;
    #pragma unroll
    for (int k = 0; k < XH_SPLITS; k++) s += g_xhp[(size_t)k*(BSZ*DIMC*MODE) + i];
    g_xh[i] = s;
}

// ---------------- xh1[b, i*16+j, k] = sum_l xh[b,i,l] * HT[j,l,k] ----------
__global__ void __launch_bounds__(256) k_xh1(){
    int b = blockIdx.x, j = blockIdx.y;
    __shared__ float xs[64][128];
    __shared__ float Bs[16][128];
    int tid = threadIdx.x, rg = tid >> 5, cg = tid & 31;
    {
        const float4* src = (const float4*)&g_xh[(size_t)b*DIMC*MODE];
        float4* dst = (float4*)&xs[0][0];
        for (int i = tid; i < 64*128/4; i += 256) dst[i] = src[i];
    }
    float acc[8][4] = {};
    for (int kt = 0; kt < 8; kt++){
        int kkB = tid >> 4, n8 = (tid & 15) * 8;
        const float* bsrc = &g_HT[((size_t)j*MODE + kt*16 + kkB)*MODE + n8];
        float4 bv0 = *(const float4*)bsrc, bv1 = *(const float4*)(bsrc + 4);
        __syncthreads();
        *(float4*)&Bs[kkB][n8] = bv0; *(float4*)&Bs[kkB][n8+4] = bv1;
        __syncthreads();
        #pragma unroll
        for (int kk = 0; kk < 16; kk++){
            int l = kt*16 + kk;
            float a_[8];
            #pragma unroll
            for (int i_ = 0; i_ < 8; i_++) a_[i_] = xs[rg*8 + i_][l];
            float4 bv_ = *(const float4*)&Bs[kk][cg*4];
            #pragma unroll
            for (int i_ = 0; i_ < 8; i_++){
                acc[i_][0] += a_[i_]*bv_.x; acc[i_][1] += a_[i_]*bv_.y;
                acc[i_][2] += a_[i_]*bv_.z; acc[i_][3] += a_[i_]*bv_.w;
            }
        }
    }
    #pragma unroll
    for (int i = 0; i < 8; i++){
        float4 v = make_float4(acc[i][0],acc[i][1],acc[i][2],acc[i][3]);
        *(float4*)&g_xh1[((size_t)b*(DIMC*NJ) + (size_t)(rg*8 + i)*NJ + j)*MODE + cg*4] = v;
    }
}

// ---------------- W_sp reorder: WrT[p][o] = W_sp[li, i, o, j], p=i*16+j ----
__global__ void k_WrT(const float* __restrict__ W_sp, int li){
    int idx = blockIdx.x * 256 + threadIdx.x;  // < 65536
    int o = idx & 63, p = idx >> 6;
    int i = p >> 4, jj = p & 15;
    g_WrT[(size_t)p*DIMC + o] = W_sp[(((size_t)li*DIMC + i)*DIMC + o)*NJ + jj];
}

// ---------------- y split-K GEMM: y[b,o,k] = sum_p WrT[p,o] xh1[b,p,k] -----
__global__ void __launch_bounds__(256) k_y_part(){
    int b = blockIdx.x, s = blockIdx.y;
    int p0 = s * 128;
    __shared__ float As[16][65];
    __shared__ float Bs[16][128];
    int tid = threadIdx.x, rg = tid >> 5, cg = tid & 31;
    float acc[8][4] = {};
    for (int kt = 0; kt < 8; kt++){
        int kkA = tid >> 4, o4 = (tid & 15) * 4;
        float4 av = *(const float4*)&g_WrT[(size_t)(p0 + kt*16 + kkA)*DIMC + o4];
        int kkB = tid >> 4, n8 = (tid & 15) * 8;
        const float* bsrc = &g_xh1[((size_t)b*(DIMC*NJ) + p0 + kt*16 + kkB)*MODE + n8];
        float4 bv0 = *(const float4*)bsrc, bv1 = *(const float4*)(bsrc + 4);
        __syncthreads();
        As[kkA][o4+0]=av.x; As[kkA][o4+1]=av.y; As[kkA][o4+2]=av.z; As[kkA][o4+3]=av.w;
        *(float4*)&Bs[kkB][n8] = bv0; *(float4*)&Bs[kkB][n8+4] = bv1;
        __syncthreads();
        #pragma unroll
        for (int kk = 0; kk < 16; kk++) MICRO_FMA(As,Bs,kk,acc,rg,cg)
    }
    #pragma unroll
    for (int i = 0; i < 8; i++){
        float4 v = make_float4(acc[i][0],acc[i][1],acc[i][2],acc[i][3]);
        *(float4*)&g_yp[(size_t)s*(BSZ*DIMC*MODE) + ((size_t)b*DIMC + rg*8 + i)*MODE + cg*4] = v;
    }
}

__global__ void k_reduce_y(){
    int i = blockIdx.x * 256 + threadIdx.x;   // < 262144
    float s = 0.f;
    #pragma unroll
    for (int k = 0; k < Y_SPLITS; k++) s += g_yp[(size_t)k*(BSZ*DIMC*MODE) + i];
    g_y[i] = s;
}

// ------ fused layer output: h' = act( y@bases^T + W_conv@h + b_conv ) ------
// last layer: epilogue computes out = gelu(h'^T @ W1 + b1) @ W2 + b2
__global__ void __launch_bounds__(256) k_layer_out(
    const float* __restrict__ hin, float* __restrict__ hout,
    const float* __restrict__ W_conv, const float* __restrict__ b_conv, int li,
    const float* __restrict__ W1, const float* __restrict__ b1,
    const float* __restrict__ W2, const float* __restrict__ b2,
    float* __restrict__ out, int is_last)
{
    int b = blockIdx.y;
    int x0 = blockIdx.x * 128;
    __shared__ float As[16][65];
    __shared__ float Bs[16][128];
    __shared__ float Csm[64][128];
    int tid = threadIdx.x, rg = tid >> 5, cg = tid & 31;
    float acc[8][4] = {};
    for (int kt = 0; kt < 12; kt++){     // K = 128 (modes) + 64 (channels)
        int c = tid >> 2, kk4 = (tid & 3) * 4;
        float4 av;
        if (kt < 8) av = *(const float4*)&g_y[((size_t)b*DIMC + c)*MODE + kt*16 + kk4];
        else        av = *(const float4*)&W_conv[((size_t)li*DIMC + c)*DIMC + (kt-8)*16 + kk4];
        int kkB = tid >> 4, n8 = (tid & 15) * 8;
        int kg = kt*16 + kkB;
        const float* bsrc = (kt < 8) ? &g_basesT[(size_t)kg*NXS + x0 + n8]
                                     : &hin[((size_t)b*DIMC + (kg - 128))*NXS + x0 + n8];
        float4 bv0 = *(const float4*)bsrc, bv1 = *(const float4*)(bsrc + 4);
        __syncthreads();
        As[kk4+0][c]=av.x; As[kk4+1][c]=av.y; As[kk4+2][c]=av.z; As[kk4+3][c]=av.w;
        *(float4*)&Bs[kkB][n8] = bv0; *(float4*)&Bs[kkB][n8+4] = bv1;
        __syncthreads();
        #pragma unroll
        for (int kk = 0; kk < 16; kk++) MICRO_FMA(As,Bs,kk,acc,rg,cg)
    }

    if (!is_last){
        #pragma unroll
        for (int i = 0; i < 8; i++){
            int c = rg*8 + i;
            float bias = b_conv[li*DIMC + c];
            float4 v;
            v.x = gelu_f(acc[i][0] + bias);
            v.y = gelu_f(acc[i][1] + bias);
            v.z = gelu_f(acc[i][2] + bias);
            v.w = gelu_f(acc[i][3] + bias);
            *(float4*)&hout[((size_t)b*DIMC + c)*NXS + x0 + cg*4] = v;
        }
        return;
    }

    // ---- last layer: no gelu on h'; fuse fc1(gelu)+fc2 ----
    #pragma unroll
    for (int i = 0; i < 8; i++){
        int c = rg*8 + i;
        float bias = b_conv[li*DIMC + c];
        float4 v = make_float4(acc[i][0]+bias, acc[i][1]+bias, acc[i][2]+bias, acc[i][3]+bias);
        *(float4*)&Csm[c][cg*4] = v;
    }

    // z[x,f] = sum_c Csm[c][x] * W1[c][f];  out[x] = sum_f gelu(z+b1[f])*W2[f] + b2
    int x4 = (tid & 31) * 4;          // 4 consecutive x per thread
    int fbase = (tid >> 5) * 16;      // 16 f per warp-group
    float zacc[4][16] = {};
    for (int c0 = 0; c0 < 64; c0 += 16){
        int kk = tid >> 4, n8 = (tid & 15) * 8;
        float4 w0v = *(const float4*)&W1[(size_t)(c0 + kk)*FCD + n8];
        float4 w1v = *(const float4*)&W1[(size_t)(c0 + kk)*FCD + n8 + 4];
        __syncthreads();
        *(float4*)&Bs[kk][n8] = w0v; *(float4*)&Bs[kk][n8+4] = w1v;
        __syncthreads();
        #pragma unroll
        for (int cc = 0; cc < 16; cc++){
            float4 a4 = *(const float4*)&Csm[c0 + cc][x4];
            float bb[16];
            #pragma unroll
            for (int q = 0; q < 16; q++) bb[q] = Bs[cc][fbase + q];
            #pragma unroll
            for (int q = 0; q < 16; q++){
                zacc[0][q] += a4.x * bb[q];
                zacc[1][q] += a4.y * bb[q];
                zacc[2][q] += a4.z * bb[q];
                zacc[3][q] += a4.w * bb[q];
            }
        }
    }
    float partial[4] = {0.f,0.f,0.f,0.f};
    #pragma unroll
    for (int q = 0; q < 16; q++){
        float bb1 = b1[fbase + q];
        float w2  = W2[fbase + q];
        #pragma unroll
        for (int z = 0; z < 4; z++)
            partial[z] += gelu_f(zacc[z][q] + bb1) * w2;
    }
    __syncthreads();
    float* scratch = &Csm[0][0];      // reuse: [8 warps][128 x]
    #pragma unroll
    for (int z = 0; z < 4; z++) scratch[(tid >> 5)*128 + x4 + z] = partial[z];
    __syncthreads();
    if (tid < 128){
        float s = b2[0];
        #pragma unroll
        for (int w = 0; w < 8; w++) s += scratch[w*128 + tid];
        out[(size_t)b*NXS + x0 + tid] = s;
    }
}

// ---------------------------------------------------------------------------
extern "C" void kernel_launch(void* const* d_in, const int* in_sizes, int n_in,
                              void* d_out, int out_size){
    (void)in_sizes; (void)n_in; (void)out_size;
    const float* x      = (const float*)d_in[0];
    const float* bases  = (const float*)d_in[1];
    const float* wbases = (const float*)d_in[2];
    const float* product= (const float*)d_in[3];
    const float* Do     = (const float*)d_in[4];
    const float* Di     = (const float*)d_in[5];
    const float* A      = (const float*)d_in[6];
    const float* Bm     = (const float*)d_in[7];
    const float* W_sp   = (const float*)d_in[8];
    const float* W_conv = (const float*)d_in[9];
    const float* b_conv = (const float*)d_in[10];
    const float* W0     = (const float*)d_in[11];
    const float* b0     = (const float*)d_in[12];
    const float* W1     = (const float*)d_in[13];
    const float* b1     = (const float*)d_in[14];
    const float* W2     = (const float*)d_in[15];
    const float* b2     = (const float*)d_in[16];
    float* out = (float*)d_out;

    float *hA = nullptr, *hB = nullptr;
    cudaGetSymbolAddress((void**)&hA, g_h);
    cudaGetSymbolAddress((void**)&hB, g_h2);

    k_transpose<<<dim3(NXS/32, MODE/32), dim3(32,8)>>>(bases);
    k_buildHT<<<dim3(NJ, MODE), MODE>>>(Do, Di, product, A, Bm);
    k_fc0<<<(BSZ*DIMC*NXS)/256, 256>>>(x, W0, b0);

    const float* hin = hA;
    float* hout = hB;
    for (int li = 0; li < N_LAYERS; li++){
        k_xh_part<<<dim3(BSZ, XH_SPLITS), 256>>>(hin, wbases);
        k_reduce_xh<<<(BSZ*DIMC*MODE)/256, 256>>>();
        k_xh1<<<dim3(BSZ, NJ), 256>>>();
        k_WrT<<<(NJ*DIMC*DIMC)/256, 256>>>(W_sp, li);
        k_y_part<<<dim3(BSZ, Y_SPLITS), 256>>>();
        k_reduce_y<<<(BSZ*DIMC*MODE)/256, 256>>>();
        k_layer_out<<<dim3(NXS/128, BSZ), 256>>>(hin, hout, W_conv, b_conv, li,
                                                 W1, b1, W2, b2, out,
                                                 (li == N_LAYERS-1) ? 1 : 0);
        const float* t = hin; hin = hout; hout = (float*)t;
    }
}

// round 3
// speedup vs baseline: 1.0682x; 1.0682x over previous
#include <cuda_runtime.h>
#include <math.h>

#define BSZ 32
#define NXS 16384
#define IN_DIM 3
#define DIMC 64
#define NJ 16
#define MODE 128
#define RANKR 4
#define FCD 128
#define N_LAYERS 3

#define XH_SPLITS 32
#define Y_SPLITS 8
#define T_SPLITS 8

// ---------------- scratch (device globals; no allocations) ----------------
__device__ float g_h [BSZ*DIMC*NXS];                 // 128 MB (h after layer0)
__device__ float g_h2[BSZ*DIMC*NXS];                 // 128 MB (h after layer1)
__device__ float g_basesT[MODE*NXS];                 // 8 MB
__device__ float g_xT[BSZ*IN_DIM*NXS];               // x transposed (b,d,x)
__device__ float g_HT[NJ*MODE*MODE];                 // H^T: [j][l][k]
__device__ float g_xh [BSZ*DIMC*MODE];               // (b,c,k)
__device__ float g_xhp[XH_SPLITS*BSZ*DIMC*MODE];     // split partials
__device__ float g_xh1[BSZ*DIMC*NJ*MODE];            // (b, c*16+j, k)
__device__ float g_WrT[NJ*DIMC*DIMC];                // (p=i*16+j, o)
__device__ float g_y  [BSZ*DIMC*MODE];
__device__ float g_yp [Y_SPLITS*BSZ*DIMC*MODE];
__device__ float g_Tp [T_SPLITS*BSZ*4*MODE];         // partial T (d=3 row: colsum wbases)
__device__ float g_Wc0T[IN_DIM*DIMC];                // (d, o): W_conv0 @ W0^T transposed
__device__ float g_bias0[DIMC];

__device__ __forceinline__ float gelu_f(float v){
    return 0.5f * v * (1.0f + erff(v * 0.70710678118654752440f));
}

// ---------------- bases transpose: basesT[k][x] = bases[x][k] -------------
__global__ void k_transpose(const float* __restrict__ bases){
    __shared__ float t[32][33];
    int x0 = blockIdx.x * 32, k0 = blockIdx.y * 32;
    for (int i = threadIdx.y; i < 32; i += 8)
        t[i][threadIdx.x] = bases[(size_t)(x0 + i) * MODE + k0 + threadIdx.x];
    __syncthreads();
    for (int i = threadIdx.y; i < 32; i += 8)
        g_basesT[(size_t)(k0 + i) * NXS + x0 + threadIdx.x] = t[threadIdx.x][i];
}

// ---------------- x transpose: xT[b][d][x] = x[b][x][d] --------------------
__global__ void k_xT(const float* __restrict__ x){
    int i = blockIdx.x * 256 + threadIdx.x;     // < 32*16384*3
    int d = i % 3;
    int t = i / 3;
    int xp = t & (NXS-1);
    int b  = t >> 14;
    g_xT[((size_t)b*IN_DIM + d)*NXS + xp] = x[i];
}

// ---------------- H^T build: HT[j][l][k] = H[j][k][l] ----------------------
__global__ void k_buildHT(const float* __restrict__ Do, const float* __restrict__ Di,
                          const float* __restrict__ pr, const float* __restrict__ A,
                          const float* __restrict__ Bm){
    int j = blockIdx.x, l = blockIdx.y, k = threadIdx.x;
    float s = Do[j*MODE + k] * Di[j*MODE + l] * pr[k*MODE + l];
    #pragma unroll
    for (int r = 0; r < RANKR; r++)
        s += A[(j*RANKR + r)*MODE + k] * Bm[(j*RANKR + r)*MODE + l];
    g_HT[((size_t)j*MODE + l)*MODE + k] = s;
}

// ------- layer-0 prep: Wc0T[d][o] = sum_c W_conv[0,o,c] W0[d,c];  bias0 ----
__global__ void k_prep0(const float* __restrict__ W_conv, const float* __restrict__ W0,
                        const float* __restrict__ b0, const float* __restrict__ b_conv){
    int o = threadIdx.x;   // 64 threads
    float w0s = 0.f, w1s = 0.f, w2s = 0.f, bb = b_conv[o];
    for (int c = 0; c < DIMC; c++){
        float wc = W_conv[o*DIMC + c];
        w0s += wc * W0[0*DIMC + c];
        w1s += wc * W0[1*DIMC + c];
        w2s += wc * W0[2*DIMC + c];
        bb  += wc * b0[c];
    }
    g_Wc0T[0*DIMC + o] = w0s;
    g_Wc0T[1*DIMC + o] = w1s;
    g_Wc0T[2*DIMC + o] = w2s;
    g_bias0[o] = bb;
}

// ------- layer-0 T partials: Tp[s,b,d,k] = sum_{x in split} xT[b,d,x] wb[x,k]
//         (d=3 slot accumulates sum of wbases, for the b0 term)
__global__ void k_T(const float* __restrict__ wbases){
    int b = blockIdx.x, s = blockIdx.y;
    int x0 = s * (NXS / T_SPLITS);       // 2048 chunk
    int k = threadIdx.x;                 // 128 threads
    __shared__ float xs[3][128];
    float a0 = 0.f, a1 = 0.f, a2 = 0.f, a3 = 0.f;
    for (int xt = 0; xt < (NXS/T_SPLITS)/128; xt++){
        __syncthreads();
        xs[0][k] = g_xT[((size_t)b*IN_DIM + 0)*NXS + x0 + xt*128 + k];
        xs[1][k] = g_xT[((size_t)b*IN_DIM + 1)*NXS + x0 + xt*128 + k];
        xs[2][k] = g_xT[((size_t)b*IN_DIM + 2)*NXS + x0 + xt*128 + k];
        __syncthreads();
        #pragma unroll 8
        for (int xi = 0; xi < 128; xi++){
            float w = wbases[(size_t)(x0 + xt*128 + xi)*MODE + k];
            a0 += xs[0][xi] * w;
            a1 += xs[1][xi] * w;
            a2 += xs[2][xi] * w;
            a3 += w;
        }
    }
    size_t base = (((size_t)s*BSZ + b)*4)*MODE + k;
    g_Tp[base + 0*MODE] = a0;
    g_Tp[base + 1*MODE] = a1;
    g_Tp[base + 2*MODE] = a2;
    g_Tp[base + 3*MODE] = a3;
}

// ------- layer-0 xh: xh0[b,c,k] = sum_d W0[d,c] T[b,d,k] + b0[c]*S[k] ------
__global__ void k_xh0(const float* __restrict__ W0, const float* __restrict__ b0){
    int b = blockIdx.x;
    __shared__ float Ts[4][128];
    int tid = threadIdx.x;
    for (int e = tid; e < 4*MODE; e += 256){
        int d = e >> 7, k = e & 127;
        float s = 0.f;
        #pragma unroll
        for (int s8 = 0; s8 < T_SPLITS; s8++)
            s += g_Tp[(((size_t)s8*BSZ + b)*4 + d)*MODE + k];
        Ts[d][k] = s;
    }
    __syncthreads();
    for (int o = tid; o < DIMC*MODE; o += 256){
        int c = o >> 7, k = o & 127;
        float v = W0[0*DIMC + c]*Ts[0][k] + W0[1*DIMC + c]*Ts[1][k]
                + W0[2*DIMC + c]*Ts[2][k] + b0[c]*Ts[3][k];
        g_xh[((size_t)b*DIMC + c)*MODE + k] = v;
    }
}

// ---------------- xh split-K GEMM (layers 1,2): 128x128 tile ---------------
// xh[m,k] = sum_x h[m,x] wbases[x,k],  m = b*64+c  (2048 rows)
__global__ void __launch_bounds__(256) k_xh_part(const float* __restrict__ hin,
                                                 const float* __restrict__ wbases){
    int m0 = blockIdx.x * 128;
    int split = blockIdx.y;
    int k0 = split * (NXS / XH_SPLITS);     // 512 chunk
    __shared__ float As[16][136];           // [kk][row], row-dim contiguous
    __shared__ float Bs[16][128];
    int tid = threadIdx.x;
    int ty = tid >> 4, tx = tid & 15;       // 16x16 thread grid, 8x8 each
    float acc[8][8] = {};
    int ar = tid >> 2, aq = tid & 3;        // A staging: rows ar, ar+64; k-quad aq
    int br = tid >> 5, bc = tid & 31;       // B staging: rows br, br+8
    for (int kt = 0; kt < (NXS/XH_SPLITS)/16; kt++){
        int kg = k0 + kt*16;
        float4 a0 = *(const float4*)&hin[(size_t)(m0 + ar)*NXS + kg + aq*4];
        float4 a1 = *(const float4*)&hin[(size_t)(m0 + ar + 64)*NXS + kg + aq*4];
        float4 b0v = *(const float4*)&wbases[(size_t)(kg + br)*MODE + bc*4];
        float4 b1v = *(const float4*)&wbases[(size_t)(kg + br + 8)*MODE + bc*4];
        __syncthreads();
        As[aq*4+0][ar] = a0.x; As[aq*4+1][ar] = a0.y;
        As[aq*4+2][ar] = a0.z; As[aq*4+3][ar] = a0.w;
        As[aq*4+0][ar+64] = a1.x; As[aq*4+1][ar+64] = a1.y;
        As[aq*4+2][ar+64] = a1.z; As[aq*4+3][ar+64] = a1.w;
        *(float4*)&Bs[br][bc*4] = b0v;
        *(float4*)&Bs[br+8][bc*4] = b1v;
        __syncthreads();
        #pragma unroll
        for (int kk = 0; kk < 16; kk++){
            float a[8], b[8];
            *(float4*)&a[0] = *(const float4*)&As[kk][ty*8];
            *(float4*)&a[4] = *(const float4*)&As[kk][ty*8+4];
            *(float4*)&b[0] = *(const float4*)&Bs[kk][tx*8];
            *(float4*)&b[4] = *(const float4*)&Bs[kk][tx*8+4];
            #pragma unroll
            for (int i = 0; i < 8; i++)
                #pragma unroll
                for (int j = 0; j < 8; j++)
                    acc[i][j] += a[i]*b[j];
        }
    }
    float* dst = &g_xhp[(size_t)split*(BSZ*DIMC*MODE)];
    #pragma unroll
    for (int i = 0; i < 8; i++){
        int m = m0 + ty*8 + i;
        *(float4*)&dst[(size_t)m*MODE + tx*8]     = make_float4(acc[i][0],acc[i][1],acc[i][2],acc[i][3]);
        *(float4*)&dst[(size_t)m*MODE + tx*8 + 4] = make_float4(acc[i][4],acc[i][5],acc[i][6],acc[i][7]);
    }
}

__global__ void k_reduce_xh(){
    int i = blockIdx.x * 256 + threadIdx.x;   // < 262144
    float s = 0.f;
    #pragma unroll
    for (int k = 0; k < XH_SPLITS; k++) s += g_xhp[(size_t)k*(BSZ*DIMC*MODE) + i];
    g_xh[i] = s;
}

// ---------------- xh1[b, c*16+j, k] = sum_l xh[b,c,l] * HT[j,l,k] ----------
__global__ void __launch_bounds__(256) k_xh1(){
    int b = blockIdx.x, j = blockIdx.y;
    __shared__ float xs[64][128];
    __shared__ float Bs[16][128];
    int tid = threadIdx.x, rg = tid >> 5, cg = tid & 31;
    {
        const float4* src = (const float4*)&g_xh[(size_t)b*DIMC*MODE];
        float4* dst = (float4*)&xs[0][0];
        for (int i = tid; i < 64*128/4; i += 256) dst[i] = src[i];
    }
    float acc[8][4] = {};
    for (int kt = 0; kt < 8; kt++){
        int kkB = tid >> 4, n8 = (tid & 15) * 8;
        const float* bsrc = &g_HT[((size_t)j*MODE + kt*16 + kkB)*MODE + n8];
        float4 bv0 = *(const float4*)bsrc, bv1 = *(const float4*)(bsrc + 4);
        __syncthreads();
        *(float4*)&Bs[kkB][n8] = bv0; *(float4*)&Bs[kkB][n8+4] = bv1;
        __syncthreads();
        #pragma unroll
        for (int kk = 0; kk < 16; kk++){
            int l = kt*16 + kk;
            float a_[8];
            #pragma unroll
            for (int i_ = 0; i_ < 8; i_++) a_[i_] = xs[rg*8 + i_][l];
            float4 bv_ = *(const float4*)&Bs[kk][cg*4];
            #pragma unroll
            for (int i_ = 0; i_ < 8; i_++){
                acc[i_][0] += a_[i_]*bv_.x; acc[i_][1] += a_[i_]*bv_.y;
                acc[i_][2] += a_[i_]*bv_.z; acc[i_][3] += a_[i_]*bv_.w;
            }
        }
    }
    #pragma unroll
    for (int i = 0; i < 8; i++){
        float4 v = make_float4(acc[i][0],acc[i][1],acc[i][2],acc[i][3]);
        *(float4*)&g_xh1[((size_t)b*(DIMC*NJ) + (size_t)(rg*8 + i)*NJ + j)*MODE + cg*4] = v;
    }
}

// ---------------- W_sp reorder: WrT[p][o] = W_sp[li, i, o, j], p=i*16+j ----
__global__ void k_WrT(const float* __restrict__ W_sp, int li){
    int idx = blockIdx.x * 256 + threadIdx.x;  // < 65536
    int o = idx & 63, p = idx >> 6;
    int i = p >> 4, jj = p & 15;
    g_WrT[(size_t)p*DIMC + o] = W_sp[(((size_t)li*DIMC + i)*DIMC + o)*NJ + jj];
}

// ---------------- y split-K GEMM: y[b,o,k] = sum_p WrT[p,o] xh1[b,p,k] -----
__global__ void __launch_bounds__(256) k_y_part(){
    int b = blockIdx.x, s = blockIdx.y;
    int p0 = s * 128;
    __shared__ float As[16][65];
    __shared__ float Bs[16][128];
    int tid = threadIdx.x, rg = tid >> 5, cg = tid & 31;
    float acc[8][4] = {};
    for (int kt = 0; kt < 8; kt++){
        int kkA = tid >> 4, o4 = (tid & 15) * 4;
        float4 av = *(const float4*)&g_WrT[(size_t)(p0 + kt*16 + kkA)*DIMC + o4];
        int kkB = tid >> 4, n8 = (tid & 15) * 8;
        const float* bsrc = &g_xh1[((size_t)b*(DIMC*NJ) + p0 + kt*16 + kkB)*MODE + n8];
        float4 bv0 = *(const float4*)bsrc, bv1 = *(const float4*)(bsrc + 4);
        __syncthreads();
        As[kkA][o4+0]=av.x; As[kkA][o4+1]=av.y; As[kkA][o4+2]=av.z; As[kkA][o4+3]=av.w;
        *(float4*)&Bs[kkB][n8] = bv0; *(float4*)&Bs[kkB][n8+4] = bv1;
        __syncthreads();
        #pragma unroll
        for (int kk = 0; kk < 16; kk++){
            float a_[8];
            #pragma unroll
            for (int i_ = 0; i_ < 8; i_++) a_[i_] = As[kk][rg*8 + i_];
            float4 bv_ = *(const float4*)&Bs[kk][cg*4];
            #pragma unroll
            for (int i_ = 0; i_ < 8; i_++){
                acc[i_][0] += a_[i_]*bv_.x; acc[i_][1] += a_[i_]*bv_.y;
                acc[i_][2] += a_[i_]*bv_.z; acc[i_][3] += a_[i_]*bv_.w;
            }
        }
    }
    #pragma unroll
    for (int i = 0; i < 8; i++){
        float4 v = make_float4(acc[i][0],acc[i][1],acc[i][2],acc[i][3]);
        *(float4*)&g_yp[(size_t)s*(BSZ*DIMC*MODE) + ((size_t)b*DIMC + rg*8 + i)*MODE + cg*4] = v;
    }
}

__global__ void k_reduce_y(){
    int i = blockIdx.x * 256 + threadIdx.x;   // < 262144
    float s = 0.f;
    #pragma unroll
    for (int k = 0; k < Y_SPLITS; k++) s += g_yp[(size_t)k*(BSZ*DIMC*MODE) + i];
    g_y[i] = s;
}

// ====== fused layer output: 64 x 256 tile ==================================
// h'[b,o,x] = y[b,o,:]@basesT[:,x] + conv_term + bias[o]
//   layers 1,2: conv K-range = 64 channels of hin (tiles 8..11)
//   layer 0   : conv K-range = 3 x-channels via Wc0T / g_xT   (tail3)
// non-last: hout = gelu(h'); last: out = gelu(h'^T@W1+b1)@W2+b2 (fused,
// processed in two 128-column halves so Csm fits in smem)
#define POOL_FLOATS (64*132 + 16*128)
__global__ void __launch_bounds__(256) k_L(
    const float* __restrict__ hin, float* __restrict__ hout,
    const float* __restrict__ Wconv_l, const float* __restrict__ biasv,
    const float* __restrict__ W1, const float* __restrict__ b1,
    const float* __restrict__ W2, const float* __restrict__ b2,
    float* __restrict__ out, int tail3, int is_last)
{
    __shared__ float pool[POOL_FLOATS];
    float (*As)[72]  = (float(*)[72])pool;             // 16*72  = 1152 floats
    float (*Bs)[256] = (float(*)[256])(pool + 1152);   // 16*256 = 4096 floats
    float (*Csm)[132] = (float(*)[132])pool;           // epilogue: 64*132
    float (*W1s)[128] = (float(*)[128])(pool + 64*132);// epilogue: 16*128

    int b = blockIdx.y;
    int x0 = blockIdx.x * 256;
    int tid = threadIdx.x;
    int ty = tid >> 5, tx = tid & 31;       // rows ty*8..+7, cols tx*8..+7
    float acc[8][8] = {};

    int ar = tid >> 2, aq = tid & 3;        // A staging: 64 rows x 16 k, 1 float4/thr
    int brr = tid >> 4, bcc = tid & 15;     // B staging: 16 rows, 4 float4/thr
    int nkt = tail3 ? 8 : 12;
    for (int kt = 0; kt < nkt; kt++){
        float4 av;
        if (kt < 8) av = *(const float4*)&g_y[((size_t)b*DIMC + ar)*MODE + kt*16 + aq*4];
        else        av = *(const float4*)&Wconv_l[(size_t)ar*DIMC + (kt-8)*16 + aq*4];
        int kg = kt*16 + brr;
        const float* bptr = (kt < 8) ? &g_basesT[(size_t)kg*NXS + x0]
                                     : &hin[((size_t)b*DIMC + (kg - 128))*NXS + x0];
        float4 bv[4];
        #pragma unroll
        for (int s = 0; s < 4; s++) bv[s] = *(const float4*)&bptr[(bcc + 16*s)*4];
        __syncthreads();
        As[aq*4+0][ar] = av.x; As[aq*4+1][ar] = av.y;
        As[aq*4+2][ar] = av.z; As[aq*4+3][ar] = av.w;
        #pragma unroll
        for (int s = 0; s < 4; s++) *(float4*)&Bs[brr][(bcc + 16*s)*4] = bv[s];
        __syncthreads();
        #pragma unroll
        for (int kk = 0; kk < 16; kk++){
            float a[8], bb[8];
            *(float4*)&a[0] = *(const float4*)&As[kk][ty*8];
            *(float4*)&a[4] = *(const float4*)&As[kk][ty*8+4];
            *(float4*)&bb[0] = *(const float4*)&Bs[kk][tx*8];
            *(float4*)&bb[4] = *(const float4*)&Bs[kk][tx*8+4];
            #pragma unroll
            for (int i = 0; i < 8; i++)
                #pragma unroll
                for (int j = 0; j < 8; j++)
                    acc[i][j] += a[i]*bb[j];
        }
    }
    if (tail3){
        // K tail of 3: Wc0T (3x64) x xT (3x256)
        __syncthreads();
        if (tid < 192){
            int d = tid >> 6, r = tid & 63;
            As[d][r] = g_Wc0T[d*DIMC + r];
        }
        if (tid < 192){
            int d = tid / 64, c4 = tid % 64;
            *(float4*)&Bs[d][c4*4] =
                *(const float4*)&g_xT[((size_t)b*IN_DIM + d)*NXS + x0 + c4*4];
        }
        __syncthreads();
        #pragma unroll
        for (int kk = 0; kk < 3; kk++){
            float a[8], bb[8];
            *(float4*)&a[0] = *(const float4*)&As[kk][ty*8];
            *(float4*)&a[4] = *(const float4*)&As[kk][ty*8+4];
            *(float4*)&bb[0] = *(const float4*)&Bs[kk][tx*8];
            *(float4*)&bb[4] = *(const float4*)&Bs[kk][tx*8+4];
            #pragma unroll
            for (int i = 0; i < 8; i++)
                #pragma unroll
                for (int j = 0; j < 8; j++)
                    acc[i][j] += a[i]*bb[j];
        }
    }
    const float* bvec = tail3 ? g_bias0 : biasv;

    if (!is_last){
        #pragma unroll
        for (int i = 0; i < 8; i++){
            int c = ty*8 + i;
            float bias = bvec[c];
            float4 v0, v1;
            v0.x = gelu_f(acc[i][0]+bias); v0.y = gelu_f(acc[i][1]+bias);
            v0.z = gelu_f(acc[i][2]+bias); v0.w = gelu_f(acc[i][3]+bias);
            v1.x = gelu_f(acc[i][4]+bias); v1.y = gelu_f(acc[i][5]+bias);
            v1.z = gelu_f(acc[i][6]+bias); v1.w = gelu_f(acc[i][7]+bias);
            float* dst = &hout[((size_t)b*DIMC + c)*NXS + x0 + tx*8];
            *(float4*)dst = v0; *(float4*)(dst+4) = v1;
        }
        return;
    }

    // ---- last layer: h' (no gelu) -> fused fc1(gelu) + fc2, two 128-col halves
    int xl4 = (tid & 31) * 4;           // 4 x-values per thread (within half)
    int fb  = (tid >> 5) * 16;          // 16 f per warp
    #pragma unroll 1
    for (int hh = 0; hh < 2; hh++){
        __syncthreads();                 // As/Bs (or prior half) dead
        if ((tx >> 4) == hh){            // this thread owns cols in current half
            int xloc = (tx & 15) * 8;
            #pragma unroll
            for (int i = 0; i < 8; i++){
                int c = ty*8 + i;
                float bias = bvec[c];
                *(float4*)&Csm[c][xloc]     = make_float4(acc[i][0]+bias, acc[i][1]+bias,
                                                          acc[i][2]+bias, acc[i][3]+bias);
                *(float4*)&Csm[c][xloc + 4] = make_float4(acc[i][4]+bias, acc[i][5]+bias,
                                                          acc[i][6]+bias, acc[i][7]+bias);
            }
        }
        __syncthreads();

        float zacc[4][16] = {};
        for (int c0 = 0; c0 < 64; c0 += 16){
            int kk = tid >> 4, c4 = tid & 15;
            float4 w0v = *(const float4*)&W1[(size_t)(c0 + kk)*FCD + c4*4];
            float4 w1v = *(const float4*)&W1[(size_t)(c0 + kk)*FCD + (c4+16)*4];
            __syncthreads();
            *(float4*)&W1s[kk][c4*4]      = w0v;
            *(float4*)&W1s[kk][(c4+16)*4] = w1v;
            __syncthreads();
            #pragma unroll
            for (int cc = 0; cc < 16; cc++){
                float4 a4 = *(const float4*)&Csm[c0 + cc][xl4];
                #pragma unroll
                for (int q = 0; q < 16; q++){
                    float bb = W1s[cc][fb + q];
                    zacc[0][q] += a4.x * bb;
                    zacc[1][q] += a4.y * bb;
                    zacc[2][q] += a4.z * bb;
                    zacc[3][q] += a4.w * bb;
                }
            }
        }
        float part[4] = {0.f,0.f,0.f,0.f};
        #pragma unroll
        for (int q = 0; q < 16; q++){
            float b1v = b1[fb + q];
            float w2v = W2[fb + q];
            #pragma unroll
            for (int z = 0; z < 4; z++)
                part[z] += gelu_f(zacc[z][q] + b1v) * w2v;
        }
        __syncthreads();
        float* scratch = &W1s[0][0];   // [8 warps][128]
        *(float4*)&scratch[(tid >> 5)*128 + xl4] = make_float4(part[0],part[1],part[2],part[3]);
        __syncthreads();
        if (tid < 128){
            float s = b2[0];
            #pragma unroll
            for (int w = 0; w < 8; w++) s += scratch[w*128 + tid];
            out[(size_t)b*NXS + x0 + hh*128 + tid] = s;
        }
    }
}

// ---------------------------------------------------------------------------
extern "C" void kernel_launch(void* const* d_in, const int* in_sizes, int n_in,
                              void* d_out, int out_size){
    (void)in_sizes; (void)n_in; (void)out_size;
    const float* x      = (const float*)d_in[0];
    const float* bases  = (const float*)d_in[1];
    const float* wbases = (const float*)d_in[2];
    const float* product= (const float*)d_in[3];
    const float* Do     = (const float*)d_in[4];
    const float* Di     = (const float*)d_in[5];
    const float* A      = (const float*)d_in[6];
    const float* Bm     = (const float*)d_in[7];
    const float* W_sp   = (const float*)d_in[8];
    const float* W_conv = (const float*)d_in[9];
    const float* b_conv = (const float*)d_in[10];
    const float* W0     = (const float*)d_in[11];
    const float* b0     = (const float*)d_in[12];
    const float* W1     = (const float*)d_in[13];
    const float* b1     = (const float*)d_in[14];
    const float* W2     = (const float*)d_in[15];
    const float* b2     = (const float*)d_in[16];
    float* out = (float*)d_out;

    float *hA = nullptr, *hB = nullptr;
    cudaGetSymbolAddress((void**)&hA, g_h);
    cudaGetSymbolAddress((void**)&hB, g_h2);

    k_transpose<<<dim3(NXS/32, MODE/32), dim3(32,8)>>>(bases);
    k_buildHT<<<dim3(NJ, MODE), MODE>>>(Do, Di, product, A, Bm);
    k_xT<<<(BSZ*NXS*IN_DIM)/256, 256>>>(x);
    k_prep0<<<1, DIMC>>>(W_conv, W0, b0, b_conv);

    // ---- layer 0 (h0 never materialized) ----
    k_T<<<dim3(BSZ, T_SPLITS), MODE>>>(wbases);
    k_xh0<<<BSZ, 256>>>(W0, b0);
    k_xh1<<<dim3(BSZ, NJ), 256>>>();
    k_WrT<<<(NJ*DIMC*DIMC)/256, 256>>>(W_sp, 0);
    k_y_part<<<dim3(BSZ, Y_SPLITS), 256>>>();
    k_reduce_y<<<(BSZ*DIMC*MODE)/256, 256>>>();
    k_L<<<dim3(NXS/256, BSZ), 256>>>(hA /*unused*/, hA, nullptr, nullptr,
                                     W1, b1, W2, b2, out, /*tail3=*/1, /*is_last=*/0);

    // ---- layers 1,2 ----
    const float* hin = hA;
    float* hout = hB;
    for (int li = 1; li < N_LAYERS; li++){
        k_xh_part<<<dim3((BSZ*DIMC)/128, XH_SPLITS), 256>>>(hin, wbases);
        k_reduce_xh<<<(BSZ*DIMC*MODE)/256, 256>>>();
        k_xh1<<<dim3(BSZ, NJ), 256>>>();
        k_WrT<<<(NJ*DIMC*DIMC)/256, 256>>>(W_sp, li);
        k_y_part<<<dim3(BSZ, Y_SPLITS), 256>>>();
        k_reduce_y<<<(BSZ*DIMC*MODE)/256, 256>>>();
        k_L<<<dim3(NXS/256, BSZ), 256>>>(hin, hout,
                                         &W_conv[(size_t)li*DIMC*DIMC],
                                         &b_conv[(size_t)li*DIMC],
                                         W1, b1, W2, b2, out,
                                         /*tail3=*/0, /*is_last=*/(li == N_LAYERS-1) ? 1 : 0);
        const float* t = hin; hin = hout; hout = (float*)t;
    }
}